// round 8
// baseline (speedup 1.0000x reference)
#include <cuda_runtime.h>
#include <math.h>

typedef unsigned long long ull;

// ---------------------------------------------------------------------------
// fma.rn.f32x2: d(pair) += a(pair) * b(pair). Operands come straight from
// LDS.64 (slab values pre-duplicated, weights pre-paired) -> no pack MOVs.
// ---------------------------------------------------------------------------
__device__ __forceinline__ void ffma2(ull& d, ull a, ull b) {
    asm("fma.rn.f32x2 %0, %1, %2, %0;" : "+l"(d) : "l"(a), "l"(b));
}
__device__ __forceinline__ void unpack2(ull v, float& lo, float& hi) {
    asm("mov.b64 {%0, %1}, %2;" : "=f"(lo), "=f"(hi) : "l"(v));
}

// ---------------------------------------------------------------------------
// Scratch (no allocations allowed -> static __device__ arrays)
// ---------------------------------------------------------------------------
__device__ float g_h1[256 * 3 * 50625];  // [B,3,15,15,15,15]
__device__ float g_h2[256 * 3 * 20736];  // [B,3,12,12,12,12]
__device__ float g_h3[256 * 4 * 6561];   // [B,4,9,9,9,9]
__device__ float g_h4[256 * 5 * 1296];   // [B,5,6,6,6,6]
__device__ float g_h5[256 * 5 * 256];    // [B,5,4,4,4,4] == [B,1280]

__host__ __device__ constexpr int odd_ge(int v) { return (v & 1) ? v : v + 1; }

// ---------------------------------------------------------------------------
// 4D conv + bias + relu. FFMA2 packed over OUTPUT-CHANNEL pairs.
//   in : [B,CIN,S,S,S,S]; w: [COUT,CIN,K,K,K,K]; out: [B,COUT,T,T,T,T]
// Block = NS slices of (b,ow); each slice's oz range split ZSPL ways.
// Slab staged as float2 (v,v); weights staged as co-pairs (w[2p],w[2p+1]).
// Thread = (slice, z-chunk, ox, oy); acc[NP][OZB] = co-pair accumulators.
// ---------------------------------------------------------------------------
template <int S, int K, int CIN, int COUT, int ZSPL, int NS, int BLK, int MINB>
__global__ void __launch_bounds__(BLK, MINB)
conv4d_relu_cp(const float* __restrict__ x,
               const float* __restrict__ w,
               const float* __restrict__ bias,
               float* __restrict__ y)
{
    constexpr int T    = S - K + 1;
    constexpr int TT   = T * T;
    constexpr int OZB  = (T + ZSPL - 1) / ZSPL;      // oz per chunk
    constexpr int NP   = (COUT + 1) / 2;             // co pairs (padded)
    constexpr int NR   = OZB + K - 1;                // row window (f2 entries)
    // row stride in f2 units: odd (conflict-free LDS.64) and >= window reach
    constexpr int RSD  = odd_ge((S > (ZSPL * OZB + K - 1)) ? S : (ZSPL * OZB + K - 1));
    constexpr int S3   = S * S * S;
    constexpr int SLABF2 = K * S * S * RSD;          // f2 per slice slab
    constexpr int CK4  = CIN * K * K * K * K;
    constexpr int WNP  = CK4 * NP;                   // f2 weight entries
    constexpr int PERS = ZSPL * TT;

    extern __shared__ float2 smf2[];
    float2* wsm   = smf2;            // [WNP]  (w[2p], w[2p+1]) per (rest,p)
    float2* slab0 = smf2 + WNP;      // [NS*SLABF2] (v,v) duplicated inputs

    const int tid = threadIdx.x;

    // stage co-paired weights: entry i -> (rest = ci,kw,kx,ky,kz ; p)
    for (int i = tid; i < WNP; i += BLK) {
        int rest = i / NP, p = i - rest * NP;
        int co0 = 2 * p, co1 = co0 + 1;
        float v0 = w[co0 * CK4 + rest];
        float v1 = (co1 < COUT) ? w[co1 * CK4 + rest] : 0.f;
        wsm[i] = make_float2(v0, v1);
    }

    const int s   = tid / PERS;
    const int r0  = tid - s * PERS;
    const int zc  = r0 / TT;
    const int rr  = r0 - zc * TT;
    const int ox  = rr / T;
    const int oy  = rr - ox * T;
    const bool active = (tid < NS * PERS);
    const int slice = blockIdx.x * NS + s;
    const int b_t   = slice / T;
    const int ow_t  = slice % T;
    const int oz0   = zc * OZB;
    const float2* slab = slab0 + s * SLABF2;

    ull acc[NP][OZB];
#pragma unroll
    for (int p = 0; p < NP; ++p)
#pragma unroll
        for (int oz = 0; oz < OZB; ++oz) acc[p][oz] = 0ull;

    for (int ci = 0; ci < CIN; ++ci) {
        __syncthreads();   // protect slabs (and, on ci=0, weights) for readers
        for (int i = tid; i < NS * K * S3; i += BLK) {
            int ss = i / (K * S3);
            int r  = i - ss * (K * S3);
            int sl = blockIdx.x * NS + ss;
            int bb = sl / T, oww = sl % T;
            int kw = r / S3;
            int r1 = r - kw * S3;
            int xx = r1 / (S * S);
            int r2i = r1 - xx * (S * S);
            int yy = r2i / S;
            int zz = r2i - yy * S;
            float v = x[((size_t)(bb * CIN + ci) * S + oww) * S3 + r];
            slab0[ss * SLABF2 + ((kw * S + xx) * S + yy) * RSD + zz] =
                make_float2(v, v);
        }
        __syncthreads();

        if (active) {
#pragma unroll 1
            for (int kw = 0; kw < K; ++kw)
#pragma unroll 1
            for (int kx = 0; kx < K; ++kx)
#pragma unroll 1
            for (int ky = 0; ky < K; ++ky) {
                const float2* row =
                    slab + ((kw * S + ox + kx) * S + oy + ky) * RSD + oz0;
                ull r2[NR];
#pragma unroll
                for (int j = 0; j < NR; ++j)
                    r2[j] = *reinterpret_cast<const ull*>(row + j);

                const float2* wrow =
                    wsm + ((((ci * K + kw) * K + kx) * K + ky) * K) * NP;
                ull wp[NP][K];
#pragma unroll
                for (int kz = 0; kz < K; ++kz)
#pragma unroll
                    for (int p = 0; p < NP; ++p)
                        wp[p][kz] = *reinterpret_cast<const ull*>(wrow + kz * NP + p);

#pragma unroll
                for (int oz = 0; oz < OZB; ++oz)
#pragma unroll
                    for (int p = 0; p < NP; ++p)
#pragma unroll
                        for (int kz = 0; kz < K; ++kz)
                            ffma2(acc[p][oz], r2[oz + kz], wp[p][kz]);
            }
        }
    }

    if (active) {
#pragma unroll
        for (int p = 0; p < NP; ++p) {
            int co0 = 2 * p, co1 = co0 + 1;
            float b0 = bias[co0];
            float b1 = (co1 < COUT) ? bias[co1] : 0.f;
            // base in "pre-oz" units: index = base*T + oz.
            // co coefficient inside base is T^3 (=> T^4 in the final index).
            size_t base0 = ((((size_t)b_t * COUT + co0) * T + ow_t) * T + ox) * T + oy;
            size_t base1 = base0 + (size_t)T * T * T;   // co0 -> co0+1
#pragma unroll
            for (int oz = 0; oz < OZB; ++oz) {
                if (oz0 + oz >= T) continue;
                float v0, v1;
                unpack2(acc[p][oz], v0, v1);
                float r0v = v0 + b0;
                y[base0 * T + oz0 + oz] = r0v > 0.f ? r0v : 0.f;
                if (co1 < COUT) {
                    float r1v = v1 + b1;
                    y[base1 * T + oz0 + oz] = r1v > 0.f ? r1v : 0.f;
                }
            }
        }
    }
}

// ---------------------------------------------------------------------------
// Dense head: relu(h @ dw1.T + db1) @ dw2.T + db2 -> softmax over 2 classes.
// ---------------------------------------------------------------------------
__global__ void dense_head(const float* __restrict__ h,
                           const float* __restrict__ dw1,
                           const float* __restrict__ db1,
                           const float* __restrict__ dw2,
                           const float* __restrict__ db2,
                           float* __restrict__ out)
{
    __shared__ float hb[1280];
    __shared__ float a[33];
    const int b   = blockIdx.x;
    const int tid = threadIdx.x;

    for (int i = tid; i < 1280; i += blockDim.x) hb[i] = h[b * 1280 + i];
    __syncthreads();

    const int warp = tid >> 5, lane = tid & 31;
    const int nwarps = blockDim.x >> 5;
    for (int co = warp; co < 33; co += nwarps) {
        float s = 0.f;
        for (int i = lane; i < 1280; i += 32) s += hb[i] * dw1[co * 1280 + i];
#pragma unroll
        for (int o = 16; o > 0; o >>= 1) s += __shfl_down_sync(0xffffffffu, s, o);
        if (lane == 0) {
            float v = s + db1[co];
            a[co] = v > 0.f ? v : 0.f;
        }
    }
    __syncthreads();

    if (tid == 0) {
        float z0 = db2[0], z1 = db2[1];
#pragma unroll
        for (int i = 0; i < 33; ++i) {
            z0 += a[i] * dw2[i];
            z1 += a[i] * dw2[33 + i];
        }
        float m  = fmaxf(z0, z1);
        float e0 = expf(z0 - m), e1 = expf(z1 - m);
        float inv = 1.f / (e0 + e1);
        out[2 * b]     = e0 * inv;
        out[2 * b + 1] = e1 * inv;
    }
}

// ---------------------------------------------------------------------------
// Launch
// ---------------------------------------------------------------------------
extern "C" void kernel_launch(void* const* d_in, const int* in_sizes, int n_in,
                              void* d_out, int out_size)
{
    const float* x   = (const float*)d_in[0];
    const float* w1  = (const float*)d_in[1];
    const float* b1  = (const float*)d_in[2];
    const float* w2  = (const float*)d_in[3];
    const float* b2  = (const float*)d_in[4];
    const float* w3  = (const float*)d_in[5];
    const float* b3  = (const float*)d_in[6];
    const float* w4  = (const float*)d_in[7];
    const float* b4  = (const float*)d_in[8];
    const float* w5  = (const float*)d_in[9];
    const float* b5  = (const float*)d_in[10];
    const float* dw1 = (const float*)d_in[11];
    const float* db1 = (const float*)d_in[12];
    const float* dw2 = (const float*)d_in[13];
    const float* db2 = (const float*)d_in[14];
    float* out = (float*)d_out;

    float *h1, *h2, *h3, *h4, *h5;
    cudaGetSymbolAddress((void**)&h1, g_h1);
    cudaGetSymbolAddress((void**)&h2, g_h2);
    cudaGetSymbolAddress((void**)&h3, g_h3);
    cudaGetSymbolAddress((void**)&h4, g_h4);
    cudaGetSymbolAddress((void**)&h5, g_h5);

    // L1: S=18 K=4 CIN=1 COUT=3 NP=2 ZSPL=4 NS=1 BLK=960 (900 act)
    //     RSD=19 smem=(512 + 24624)*8 = 201,088B  -> 1 blk/SM, 30 warps
    // L2: S=15 ZSPL=4 NS=1 BLK=576 (576 act) RSD=15
    //     smem=(1536 + 13500)*8 = 120,288B        -> 1 blk/SM, 18 warps
    // L3: S=12 ZSPL=3 NS=1 BLK=256 (243 act) RSD=13
    //     smem=(1536 + 7488)*8 = 72,192B          -> 3 blk/SM, 24 warps
    // L4: S=9  ZSPL=2 NS=2 BLK=144 (144 act) RSD=9
    //     smem=(3072 + 2*2916)*8 = 71,232B        -> 3 blk/SM
    // L5: S=6  K=3 ZSPL=1 NS=8 BLK=128 (128 act) RSD=7
    //     smem=(1215 + 8*756)*8 = 58,104B
    constexpr int sm1 = (512  + 1 * 4 * 18 * 18 * 19) * 8;
    constexpr int sm2 = (1536 + 1 * 4 * 15 * 15 * 15) * 8;
    constexpr int sm3 = (1536 + 1 * 4 * 12 * 12 * 13) * 8;
    constexpr int sm4 = (3072 + 2 * 4 * 9 * 9 * 9) * 8;
    constexpr int sm5 = (1215 + 8 * 3 * 6 * 6 * 7) * 8;

    cudaFuncSetAttribute((conv4d_relu_cp<18, 4, 1, 3, 4, 1, 960, 1>),
                         cudaFuncAttributeMaxDynamicSharedMemorySize, sm1);
    cudaFuncSetAttribute((conv4d_relu_cp<15, 4, 3, 3, 4, 1, 576, 1>),
                         cudaFuncAttributeMaxDynamicSharedMemorySize, sm2);
    cudaFuncSetAttribute((conv4d_relu_cp<12, 4, 3, 4, 3, 1, 256, 3>),
                         cudaFuncAttributeMaxDynamicSharedMemorySize, sm3);
    cudaFuncSetAttribute((conv4d_relu_cp<9, 4, 4, 5, 2, 2, 144, 3>),
                         cudaFuncAttributeMaxDynamicSharedMemorySize, sm4);
    cudaFuncSetAttribute((conv4d_relu_cp<6, 3, 5, 5, 1, 8, 128, 3>),
                         cudaFuncAttributeMaxDynamicSharedMemorySize, sm5);

    conv4d_relu_cp<18, 4, 1, 3, 4, 1, 960, 1><<<256 * 15,     960, sm1>>>(x,  w1, b1, h1);
    conv4d_relu_cp<15, 4, 3, 3, 4, 1, 576, 1><<<256 * 12,     576, sm2>>>(h1, w2, b2, h2);
    conv4d_relu_cp<12, 4, 3, 4, 3, 1, 256, 3><<<256 * 9,      256, sm3>>>(h2, w3, b3, h3);
    conv4d_relu_cp< 9, 4, 4, 5, 2, 2, 144, 3><<<256 * 6 / 2,  144, sm4>>>(h3, w4, b4, h4);
    conv4d_relu_cp< 6, 3, 5, 5, 1, 8, 128, 3><<<256 * 4 / 8,  128, sm5>>>(h4, w5, b5, h5);
    dense_head<<<256, 256>>>(h5, dw1, db1, dw2, db2, out);
}

// round 9
// speedup vs baseline: 1.7983x; 1.7983x over previous
#include <cuda_runtime.h>
#include <math.h>

// ---------------------------------------------------------------------------
// Conv weights in __constant__ memory (warp-uniform indices -> LDCU -> UR
// operands; the fma pipe is rt=1 for non-GPR multiplier forms).
// Sizes: w1=768, w2=2304, w3=3072, w4=5120, w5=2025 -> total 13289 floats.
// ---------------------------------------------------------------------------
__constant__ float c_w[13289];

// ---------------------------------------------------------------------------
// Scratch (no allocations allowed -> static __device__ arrays)
// ---------------------------------------------------------------------------
__device__ float g_h1[256 * 3 * 50625];  // [B,3,15,15,15,15]
__device__ float g_h2[256 * 3 * 20736];  // [B,3,12,12,12,12]
__device__ float g_h3[256 * 4 * 6561];   // [B,4,9,9,9,9]
__device__ float g_h4[256 * 5 * 1296];   // [B,5,6,6,6,6]
__device__ float g_h5[256 * 5 * 256];    // [B,5,4,4,4,4] == [B,1280]

// ---------------------------------------------------------------------------
// Generic 4D conv + bias + relu (valid padding, stride 1). R2 structure.
//   in : [B, CIN, S, S, S, S]; weights at c_w[WOFF..]; out: [B,COUT,T,...]
// Block = one (b, ow). Per ci: stage slab in[b,ci,ow..ow+K-1,:,:,:] into smem
// (z-rows padded to odd stride -> conflict-free LDS across oy lanes).
// Thread = one (ox,oy); accumulates all COUT x T outputs in registers.
// Weights read straight from __constant__ with warp-uniform indices.
// ---------------------------------------------------------------------------
template <int S, int K, int CIN, int COUT, int WOFF>
__global__ void conv4d_relu(const float* __restrict__ x,
                            const float* __restrict__ bias,
                            float* __restrict__ y)
{
    constexpr int T  = S - K + 1;
    constexpr int RS = (S & 1) ? S : S + 1;   // padded z-row stride (odd)
    constexpr int S3 = S * S * S;

    extern __shared__ float slab[];           // [K*S*S*RS] one channel slab

    const int tid = threadIdx.x;
    const int b   = blockIdx.x / T;
    const int ow  = blockIdx.x % T;

    float acc[COUT][T];
#pragma unroll
    for (int co = 0; co < COUT; ++co)
#pragma unroll
        for (int oz = 0; oz < T; ++oz) acc[co][oz] = 0.f;

    const int  ox     = tid / T;
    const int  oy     = tid % T;
    const bool active = (tid < T * T);

    for (int ci = 0; ci < CIN; ++ci) {
        __syncthreads();   // protect slab from previous iteration's readers
        const float* src = x + ((size_t)(b * CIN + ci) * S + ow) * S3;
        for (int i = tid; i < K * S3; i += blockDim.x) {
            int kw = i / S3;
            int r  = i - kw * S3;
            int xx = r / (S * S);
            int r2 = r - xx * (S * S);
            int yy = r2 / S;
            int zz = r2 - yy * S;
            slab[((kw * S + xx) * S + yy) * RS + zz] = src[i];
        }
        __syncthreads();

        if (active) {
#pragma unroll 1
            for (int kw = 0; kw < K; ++kw)
#pragma unroll 1
            for (int kx = 0; kx < K; ++kx)
#pragma unroll 1
            for (int ky = 0; ky < K; ++ky) {
                const float* row = &slab[((kw * S + ox + kx) * S + oy + ky) * RS];
                float r[S];
#pragma unroll
                for (int z = 0; z < S; ++z) r[z] = row[z];

                // weight base for this (ci,kw,kx,ky): warp-uniform
                const int wb = WOFF + (((0 * CIN + ci) * K + kw) * K + kx) * K * K + ky * K;

#pragma unroll
                for (int oz = 0; oz < T; ++oz)
#pragma unroll
                    for (int co = 0; co < COUT; ++co)
#pragma unroll
                        for (int kz = 0; kz < K; ++kz)
                            acc[co][oz] = fmaf(r[oz + kz],
                                               c_w[wb + co * (CIN * K * K * K * K) + kz],
                                               acc[co][oz]);
            }
        }
    }

    if (active) {
#pragma unroll
        for (int co = 0; co < COUT; ++co) {
            float bv = bias[co];
#pragma unroll
            for (int oz = 0; oz < T; ++oz) {
                float v = acc[co][oz] + bv;
                y[((((((size_t)b * COUT + co) * T + ow) * T + ox) * T + oy) * T) + oz] =
                    v > 0.f ? v : 0.f;
            }
        }
    }
}

// ---------------------------------------------------------------------------
// Dense head: relu(h @ dw1.T + db1) @ dw2.T + db2 -> softmax over 2 classes.
// ---------------------------------------------------------------------------
__global__ void dense_head(const float* __restrict__ h,
                           const float* __restrict__ dw1,
                           const float* __restrict__ db1,
                           const float* __restrict__ dw2,
                           const float* __restrict__ db2,
                           float* __restrict__ out)
{
    __shared__ float hb[1280];
    __shared__ float a[33];
    const int b   = blockIdx.x;
    const int tid = threadIdx.x;

    for (int i = tid; i < 1280; i += blockDim.x) hb[i] = h[b * 1280 + i];
    __syncthreads();

    const int warp = tid >> 5, lane = tid & 31;
    const int nwarps = blockDim.x >> 5;
    for (int co = warp; co < 33; co += nwarps) {
        float s = 0.f;
        for (int i = lane; i < 1280; i += 32) s += hb[i] * dw1[co * 1280 + i];
#pragma unroll
        for (int o = 16; o > 0; o >>= 1) s += __shfl_down_sync(0xffffffffu, s, o);
        if (lane == 0) {
            float v = s + db1[co];
            a[co] = v > 0.f ? v : 0.f;
        }
    }
    __syncthreads();

    if (tid == 0) {
        float z0 = db2[0], z1 = db2[1];
#pragma unroll
        for (int i = 0; i < 33; ++i) {
            z0 += a[i] * dw2[i];
            z1 += a[i] * dw2[33 + i];
        }
        float m  = fmaxf(z0, z1);
        float e0 = expf(z0 - m), e1 = expf(z1 - m);
        float inv = 1.f / (e0 + e1);
        out[2 * b]     = e0 * inv;
        out[2 * b + 1] = e1 * inv;
    }
}

// ---------------------------------------------------------------------------
// Launch
// ---------------------------------------------------------------------------
extern "C" void kernel_launch(void* const* d_in, const int* in_sizes, int n_in,
                              void* d_out, int out_size)
{
    const float* x   = (const float*)d_in[0];
    const float* w1  = (const float*)d_in[1];
    const float* b1  = (const float*)d_in[2];
    const float* w2  = (const float*)d_in[3];
    const float* b2  = (const float*)d_in[4];
    const float* w3  = (const float*)d_in[5];
    const float* b3  = (const float*)d_in[6];
    const float* w4  = (const float*)d_in[7];
    const float* b4  = (const float*)d_in[8];
    const float* w5  = (const float*)d_in[9];
    const float* b5  = (const float*)d_in[10];
    const float* dw1 = (const float*)d_in[11];
    const float* db1 = (const float*)d_in[12];
    const float* dw2 = (const float*)d_in[13];
    const float* db2 = (const float*)d_in[14];
    float* out = (float*)d_out;

    float *h1, *h2, *h3, *h4, *h5;
    cudaGetSymbolAddress((void**)&h1, g_h1);
    cudaGetSymbolAddress((void**)&h2, g_h2);
    cudaGetSymbolAddress((void**)&h3, g_h3);
    cudaGetSymbolAddress((void**)&h4, g_h4);
    cudaGetSymbolAddress((void**)&h5, g_h5);

    // Copy conv weights into constant memory (D2D async, graph-capturable).
    // Offsets: w1=0(768), w2=768(2304), w3=3072(3072), w4=6144(5120), w5=11264(2025)
    cudaMemcpyToSymbolAsync(c_w, w1,  768 * 4,     0 * 4, cudaMemcpyDeviceToDevice, 0);
    cudaMemcpyToSymbolAsync(c_w, w2, 2304 * 4,   768 * 4, cudaMemcpyDeviceToDevice, 0);
    cudaMemcpyToSymbolAsync(c_w, w3, 3072 * 4,  3072 * 4, cudaMemcpyDeviceToDevice, 0);
    cudaMemcpyToSymbolAsync(c_w, w4, 5120 * 4,  6144 * 4, cudaMemcpyDeviceToDevice, 0);
    cudaMemcpyToSymbolAsync(c_w, w5, 2025 * 4, 11264 * 4, cudaMemcpyDeviceToDevice, 0);

    // smem: one input-channel slab (z-rows padded to odd stride)
    constexpr int sm1 = 4 * 18 * 18 * 19 * 4;  // 98,496
    constexpr int sm2 = 4 * 15 * 15 * 15 * 4;  // 54,000
    constexpr int sm3 = 4 * 12 * 12 * 13 * 4;  // 29,952
    constexpr int sm4 = 4 * 9 * 9 * 9 * 4;     // 11,664
    constexpr int sm5 = 3 * 6 * 6 * 7 * 4;     //  3,024

    cudaFuncSetAttribute((conv4d_relu<18, 4, 1, 3, 0>),
                         cudaFuncAttributeMaxDynamicSharedMemorySize, sm1);
    cudaFuncSetAttribute((conv4d_relu<15, 4, 3, 3, 768>),
                         cudaFuncAttributeMaxDynamicSharedMemorySize, sm2);

    conv4d_relu<18, 4, 1, 3, 0>    <<<256 * 15, 256, sm1>>>(x,  b1, h1);
    conv4d_relu<15, 4, 3, 3, 768>  <<<256 * 12, 160, sm2>>>(h1, b2, h2);
    conv4d_relu<12, 4, 3, 4, 3072> <<<256 * 9,   96, sm3>>>(h2, b3, h3);
    conv4d_relu< 9, 4, 4, 5, 6144> <<<256 * 6,   64, sm4>>>(h3, b4, h4);
    conv4d_relu< 6, 3, 5, 5, 11264><<<256 * 4,   32, sm5>>>(h4, b5, h5);
    dense_head<<<256, 256>>>(h5, dw1, db1, dw2, db2, out);
}